// round 10
// baseline (speedup 1.0000x reference)
#include <cuda_runtime.h>
#include <cuda_fp16.h>
#include <cstdint>

// ============================================================================
// GroupedExperts: out = swiglu(x@W1+b1) @ W2 + b2   (E=8, T=2048, D=2048)
// R10: R9 with the epilogue staging pitch fixed 136 -> 144 bytes (16B-aligned
// rows for ld.shared.v4 — 136 caused the misaligned-address trap).
// fp16 mma.sync m16n8k16 pipeline, SMEM-staged coalesced GEMM1 epilogue,
// single merged fp32->fp16 prepass.
// ============================================================================

namespace {
constexpr int E_ = 8;
constexpr int T_ = 2048;
constexpr int D_ = 2048;
constexpr int F_ = 4096;

constexpr int BM = 128, BN = 128, BK = 64;
constexpr int STAGES = 3;
constexpr int NT = D_ / BK;                   // 32 k-tiles (K=2048 both GEMMs)

constexpr int BPITCH = 272;                   // B row pitch bytes (17*16 -> conflict-free)
constexpr int A_STAGE_B = BM * BK * 2;        // 16384 B (128 rows x 128B)
constexpr int B_STAGE_B = BK * BPITCH;        // 17408 B
constexpr int STAGE_B   = A_STAGE_B + B_STAGE_B;    // 33792
constexpr int SMEM_BYTES = STAGES * STAGE_B + 128;  // ~99.1 KB -> 2 CTAs/SM

constexpr int EPI_PITCH = 144;                // fp16 staging pitch bytes (16B-aligned rows)

constexpr float ALPHA_ = 1.702f;
constexpr float LIMIT_ = 7.0f;
}

// scratch (no allocations allowed): fp16 copies + fp16 activation
__device__ __half g_acth[(size_t)E_ * T_ * D_];   // 64 MiB
__device__ __half g_xh  [(size_t)E_ * T_ * D_];   // 64 MiB
__device__ __half g_w1h [(size_t)E_ * D_ * F_];   // 128 MiB
__device__ __half g_w2h [(size_t)E_ * D_ * D_];   // 64 MiB

// ---------------- PTX helpers ----------------
__device__ __forceinline__ uint32_t smem_u32(const void* p) {
    uint32_t a;
    asm("{ .reg .u64 t; cvta.to.shared.u64 t, %1; cvt.u32.u64 %0, t; }" : "=r"(a) : "l"(p));
    return a;
}
__device__ __forceinline__ uint32_t swzA(uint32_t row, uint32_t ch) {
    return row * 128u + ((ch ^ (row & 7u)) * 16u);
}
__device__ __forceinline__ void cpasync16(uint32_t dst, const void* src) {
    asm volatile("cp.async.cg.shared.global [%0], [%1], 16;" :: "r"(dst), "l"(src) : "memory");
}
__device__ __forceinline__ void cp_commit() {
    asm volatile("cp.async.commit_group;" ::: "memory");
}
template <int N>
__device__ __forceinline__ void cp_wait() {
    asm volatile("cp.async.wait_group %0;" :: "n"(N) : "memory");
}
__device__ __forceinline__ void ldsm_x4(uint32_t* r, uint32_t addr) {
    asm volatile("ldmatrix.sync.aligned.m8n8.x4.shared.b16 {%0,%1,%2,%3}, [%4];"
                 : "=r"(r[0]), "=r"(r[1]), "=r"(r[2]), "=r"(r[3]) : "r"(addr));
}
__device__ __forceinline__ void ldsm_x4_t(uint32_t* r, uint32_t addr) {
    asm volatile("ldmatrix.sync.aligned.m8n8.x4.trans.shared.b16 {%0,%1,%2,%3}, [%4];"
                 : "=r"(r[0]), "=r"(r[1]), "=r"(r[2]), "=r"(r[3]) : "r"(addr));
}
__device__ __forceinline__ void sts16(uint32_t addr, uint16_t v) {
    asm volatile("st.shared.u16 [%0], %1;" :: "r"(addr), "h"(v) : "memory");
}
__device__ __forceinline__ uint4 lds128(uint32_t addr) {
    uint4 v;
    asm volatile("ld.shared.v4.u32 {%0,%1,%2,%3}, [%4];"
                 : "=r"(v.x), "=r"(v.y), "=r"(v.z), "=r"(v.w) : "r"(addr));
    return v;
}
__device__ __forceinline__ void mma_f16(float* c, const uint32_t* a, const uint32_t* b) {
    asm volatile(
        "mma.sync.aligned.m16n8k16.row.col.f32.f16.f16.f32 "
        "{%0,%1,%2,%3}, {%4,%5,%6,%7}, {%8,%9}, {%0,%1,%2,%3};"
        : "+f"(c[0]), "+f"(c[1]), "+f"(c[2]), "+f"(c[3])
        : "r"(a[0]), "r"(a[1]), "r"(a[2]), "r"(a[3]), "r"(b[0]), "r"(b[1]));
}

// ---------------- merged pre-pass: fp32 -> fp16(rn), 3 segments ----------------
__global__ void to_half_all(const float4* __restrict__ x,
                            const float4* __restrict__ w1,
                            const float4* __restrict__ w2,
                            uint2* __restrict__ xh,
                            uint2* __restrict__ w1h,
                            uint2* __restrict__ w2h,
                            int nx, int nw1, int nw2)
{
    const int total = nx + nw1 + nw2;
    int i = blockIdx.x * blockDim.x + threadIdx.x;
    const int stride = gridDim.x * blockDim.x;
    for (; i < total; i += stride) {
        const float4* s; uint2* d; int j = i;
        if (j < nx)            { s = x;  d = xh; }
        else if (j < nx + nw1) { j -= nx;       s = w1; d = w1h; }
        else                   { j -= nx + nw1; s = w2; d = w2h; }
        float4 v = s[j];
        __half2 h0 = __floats2half2_rn(v.x, v.y);
        __half2 h1 = __floats2half2_rn(v.z, v.w);
        uint2 u;
        u.x = *reinterpret_cast<uint32_t*>(&h0);
        u.y = *reinterpret_cast<uint32_t*>(&h1);
        d[j] = u;
    }
}

// ----------------------------------------------------------------------------
// C 128x128 tile = A[128, K] @ W[K, NTOT slice 128]  (+bias, optional SwiGLU)
// ----------------------------------------------------------------------------
template <bool FUSE, int NTOT, typename OutT>
__global__ __launch_bounds__(256, 2)
void hmma_gemm_kernel(const __half* __restrict__ Ag,
                      const __half* __restrict__ Wg,
                      const float* __restrict__ biasg,
                      OutT* __restrict__ Cg)
{
    extern __shared__ float dsm[];
    const int tid  = threadIdx.x;
    const int wid  = tid >> 5;
    const int lane = tid & 31;
    const int e  = blockIdx.z;
    const int bm = blockIdx.y * BM;
    const int bn = blockIdx.x * BN;

    const __half* Ae = Ag + ((size_t)e * T_ + bm) * D_;
    const __half* We = Wg + (size_t)e * D_ * NTOT + bn;
    const float*  Be = biasg + (size_t)e * NTOT + bn;

    const uint32_t s0 = (smem_u32(dsm) + 127u) & ~127u;
    const uint32_t sEnd = s0 + STAGES * STAGE_B;

    // --- producer state: A = 1024 chunks (4/thr), B = 1024 chunks (4/thr) ---
    const int pArow = tid >> 3, pAc = tid & 7;
    const uint32_t pAoff = swzA(pArow, pAc);
    const uint32_t pAg   = (uint32_t)pArow * D_ + pAc * 8;
    const int pBk = tid >> 4, pBc = tid & 15;
    const uint32_t pBoff = (uint32_t)pBk * BPITCH + pBc * 16;
    const uint32_t pBg   = (uint32_t)pBk * NTOT + pBc * 8;

    const __half* aSrc = Ae;
    const __half* bSrc = We;
    uint32_t prodBase = s0;
    auto produce = [&]() {
        #pragma unroll
        for (int i = 0; i < 4; i++)
            cpasync16(prodBase + pAoff + i * (32u * 128u),
                      aSrc + pAg + (size_t)(32 * i) * D_);
        const uint32_t pb = prodBase + A_STAGE_B;
        #pragma unroll
        for (int i = 0; i < 4; i++)
            cpasync16(pb + pBoff + i * (16u * BPITCH),
                      bSrc + pBg + (size_t)(16 * i) * NTOT);
        cp_commit();
        aSrc += BK;
        bSrc += (size_t)BK * NTOT;
        prodBase += STAGE_B;
        if (prodBase == sEnd) prodBase = s0;
    };

    produce();
    produce();

    const int wm = (wid >> 2) * 64;
    const int wn = (wid & 3) * 32;

    float acc[4][4][4];
    #pragma unroll
    for (int mi = 0; mi < 4; mi++)
        #pragma unroll
        for (int ni = 0; ni < 4; ni++)
            #pragma unroll
            for (int v = 0; v < 4; v++) acc[mi][ni][v] = 0.0f;

    const int lrow = lane & 15;
    const int lchx = lane >> 4;
    const uint32_t rx = (uint32_t)(lrow & 7);
    uint32_t aRowOff[4];
    #pragma unroll
    for (int mi = 0; mi < 4; mi++)
        aRowOff[mi] = (uint32_t)(wm + mi * 16 + lrow) * 128u;
    const uint32_t bLaneOff = (uint32_t)(lane & 15) * BPITCH
                            + (uint32_t)((wn >> 3) + (lane >> 4)) * 16u;

    uint32_t consBase = s0;
    for (int kt = 0; kt < NT; kt++) {
        cp_wait<STAGES - 2>();
        __syncthreads();
        if (kt + STAGES - 1 < NT) produce();

        const uint32_t sA = consBase;
        const uint32_t sBl = consBase + A_STAGE_B + bLaneOff;

        uint32_t b[2][4][2];
        {
            uint32_t r[4];
            ldsm_x4_t(r, sBl);
            b[0][0][0]=r[0]; b[0][0][1]=r[1]; b[0][1][0]=r[2]; b[0][1][1]=r[3];
            ldsm_x4_t(r, sBl + 32u);
            b[0][2][0]=r[0]; b[0][2][1]=r[1]; b[0][3][0]=r[2]; b[0][3][1]=r[3];
        }

        #pragma unroll
        for (int ks = 0; ks < 4; ks++) {
            uint32_t a[4][4];
            #pragma unroll
            for (int mi = 0; mi < 4; mi++) {
                uint32_t ch = ((uint32_t)(2 * ks + lchx) ^ rx) * 16u;
                ldsm_x4(a[mi], sA + aRowOff[mi] + ch);
            }
            if (ks < 3) {
                const uint32_t nb = sBl + (uint32_t)(ks + 1) * (16u * BPITCH);
                uint32_t r[4];
                ldsm_x4_t(r, nb);
                b[(ks+1)&1][0][0]=r[0]; b[(ks+1)&1][0][1]=r[1];
                b[(ks+1)&1][1][0]=r[2]; b[(ks+1)&1][1][1]=r[3];
                ldsm_x4_t(r, nb + 32u);
                b[(ks+1)&1][2][0]=r[0]; b[(ks+1)&1][2][1]=r[1];
                b[(ks+1)&1][3][0]=r[2]; b[(ks+1)&1][3][1]=r[3];
            }
            #pragma unroll
            for (int mi = 0; mi < 4; mi++)
                #pragma unroll
                for (int ni = 0; ni < 4; ni++)
                    mma_f16(acc[mi][ni], a[mi], b[ks & 1][ni]);
        }

        consBase += STAGE_B;
        if (consBase == sEnd) consBase = s0;
    }

    // ------------------------------ epilogue ------------------------------
    if (FUSE) {
        // stage 128x64 fp16 tile in SMEM (pitch 144B), then coalesced 16B stores
        __syncthreads();                       // all warps done reading stages
        const uint32_t eb = s0;
        #pragma unroll
        for (int ni = 0; ni < 4; ni++) {
            const int cl = wn + ni * 8 + 2 * (lane & 3);
            const float b_e = Be[cl];
            const float b_o = Be[cl + 1];
            const int colp = (wn >> 1) + ni * 4 + (lane & 3);
            #pragma unroll
            for (int mi = 0; mi < 4; mi++) {
                const int rbase = wm + mi * 16 + (lane >> 2);
                #pragma unroll
                for (int h = 0; h < 2; h++) {
                    const float v0 = acc[mi][ni][2 * h + 0] + b_e;
                    const float v1 = acc[mi][ni][2 * h + 1] + b_o;
                    float g = fminf(v0, LIMIT_);
                    float l = fminf(fmaxf(v1, -LIMIT_), LIMIT_);
                    float sg = 1.0f / (1.0f + __expf(-ALPHA_ * g));
                    __half hv = __float2half_rn(g * sg * (l + 1.0f));
                    sts16(eb + (uint32_t)(rbase + 8 * h) * EPI_PITCH + colp * 2,
                          *reinterpret_cast<uint16_t*>(&hv));
                }
            }
        }
        __syncthreads();
        __half* actRow = (__half*)Cg + ((size_t)e * T_ + bm) * D_ + (bn >> 1);
        #pragma unroll
        for (int i = 0; i < 4; i++) {
            int id = tid + 256 * i;            // 1024 chunks: 128 rows x 8 x 16B
            int row = id >> 3, c = id & 7;
            uint4 v = lds128(eb + (uint32_t)row * EPI_PITCH + c * 16);
            *(uint4*)(actRow + (size_t)row * D_ + c * 8) = v;
        }
    } else {
        #pragma unroll
        for (int ni = 0; ni < 4; ni++) {
            const int cl = wn + ni * 8 + 2 * (lane & 3);
            const float b_e = Be[cl];
            const float b_o = Be[cl + 1];
            #pragma unroll
            for (int mi = 0; mi < 4; mi++) {
                const int r0 = bm + wm + mi * 16 + (lane >> 2);
                #pragma unroll
                for (int h = 0; h < 2; h++) {
                    const float v0 = acc[mi][ni][2 * h + 0] + b_e;
                    const float v1 = acc[mi][ni][2 * h + 1] + b_o;
                    const size_t row = (size_t)e * T_ + r0 + 8 * h;
                    float2 o = make_float2(v0, v1);
                    *(float2*)((float*)Cg + row * D_ + bn + cl) = o;
                }
            }
        }
    }
}

// ----------------------------------------------------------------------------
extern "C" void kernel_launch(void* const* d_in, const int* in_sizes, int n_in,
                              void* d_out, int out_size)
{
    (void)in_sizes; (void)n_in; (void)out_size;
    const float* x  = (const float*)d_in[0];
    const float* w1 = (const float*)d_in[1];
    const float* b1 = (const float*)d_in[2];
    const float* w2 = (const float*)d_in[3];
    const float* b2 = (const float*)d_in[4];
    float* out = (float*)d_out;

    __half *acth, *xh, *w1h, *w2h;
    cudaGetSymbolAddress((void**)&acth, g_acth);
    cudaGetSymbolAddress((void**)&xh,   g_xh);
    cudaGetSymbolAddress((void**)&w1h,  g_w1h);
    cudaGetSymbolAddress((void**)&w2h,  g_w2h);

    static bool attr_done = false;
    if (!attr_done) {
        cudaFuncSetAttribute(hmma_gemm_kernel<true,  F_, __half>,
                             cudaFuncAttributeMaxDynamicSharedMemorySize, SMEM_BYTES);
        cudaFuncSetAttribute(hmma_gemm_kernel<false, D_, float>,
                             cudaFuncAttributeMaxDynamicSharedMemorySize, SMEM_BYTES);
        attr_done = true;
    }

    // merged pre-pass: fp32 -> fp16 once (x, w1, w2)
    const int nx  = E_ * T_ * D_ / 4;
    const int nw1 = E_ * D_ * F_ / 4;
    const int nw2 = E_ * D_ * D_ / 4;
    to_half_all<<<4096, 256>>>((const float4*)x, (const float4*)w1, (const float4*)w2,
                               (uint2*)xh, (uint2*)w1h, (uint2*)w2h, nx, nw1, nw2);

    // GEMM1 + bias + SwiGLU -> act (fp16)   (M=2048, N=4096, K=2048)
    dim3 g1(F_ / BN, T_ / BM, E_);
    hmma_gemm_kernel<true,  F_, __half><<<g1, 256, SMEM_BYTES>>>(xh, w1h, b1, acth);

    // GEMM2 + bias -> out (fp32)            (M=2048, N=2048, K=2048)
    dim3 g2(D_ / BN, T_ / BM, E_);
    hmma_gemm_kernel<false, D_, float><<<g2, 256, SMEM_BYTES>>>(acth, w2h, b2, out);
}

// round 11
// speedup vs baseline: 1.0721x; 1.0721x over previous
#include <cuda_runtime.h>
#include <cuda_fp16.h>
#include <cstdint>

// ============================================================================
// GroupedExperts: out = swiglu(x@W1+b1) @ W2 + b2   (E=8, T=2048, D=2048)
// R11: R8's verified fp16 mma.sync pipeline + direct-store epilogue (R10's
// SMEM staging regressed -> reverted), merged fp32->fp16 prepass (kept),
// and a statically-unrolled 3-stage mainloop (compile-time stage addresses,
// no rotate/wrap ALU).
// ============================================================================

namespace {
constexpr int E_ = 8;
constexpr int T_ = 2048;
constexpr int D_ = 2048;
constexpr int F_ = 4096;

constexpr int BM = 128, BN = 128, BK = 64;
constexpr int STAGES = 3;
constexpr int NT = D_ / BK;                   // 32 k-tiles (K=2048 both GEMMs)

constexpr int BPITCH = 272;                   // B row pitch bytes (17*16 -> conflict-free)
constexpr int A_STAGE_B = BM * BK * 2;        // 16384 B (128 rows x 128B)
constexpr int B_STAGE_B = BK * BPITCH;        // 17408 B
constexpr int STAGE_B   = A_STAGE_B + B_STAGE_B;    // 33792
constexpr int SMEM_BYTES = STAGES * STAGE_B + 128;  // ~99.1 KB -> 2 CTAs/SM

constexpr float ALPHA_ = 1.702f;
constexpr float LIMIT_ = 7.0f;
}

// scratch (no allocations allowed): fp16 copies + fp16 activation
__device__ __half g_acth[(size_t)E_ * T_ * D_];   // 64 MiB
__device__ __half g_xh  [(size_t)E_ * T_ * D_];   // 64 MiB
__device__ __half g_w1h [(size_t)E_ * D_ * F_];   // 128 MiB
__device__ __half g_w2h [(size_t)E_ * D_ * D_];   // 64 MiB

// ---------------- PTX helpers ----------------
__device__ __forceinline__ uint32_t smem_u32(const void* p) {
    uint32_t a;
    asm("{ .reg .u64 t; cvta.to.shared.u64 t, %1; cvt.u32.u64 %0, t; }" : "=r"(a) : "l"(p));
    return a;
}
__device__ __forceinline__ uint32_t swzA(uint32_t row, uint32_t ch) {
    return row * 128u + ((ch ^ (row & 7u)) * 16u);
}
__device__ __forceinline__ void cpasync16(uint32_t dst, const void* src) {
    asm volatile("cp.async.cg.shared.global [%0], [%1], 16;" :: "r"(dst), "l"(src) : "memory");
}
__device__ __forceinline__ void cp_commit() {
    asm volatile("cp.async.commit_group;" ::: "memory");
}
template <int N>
__device__ __forceinline__ void cp_wait() {
    asm volatile("cp.async.wait_group %0;" :: "n"(N) : "memory");
}
__device__ __forceinline__ void ldsm_x4(uint32_t* r, uint32_t addr) {
    asm volatile("ldmatrix.sync.aligned.m8n8.x4.shared.b16 {%0,%1,%2,%3}, [%4];"
                 : "=r"(r[0]), "=r"(r[1]), "=r"(r[2]), "=r"(r[3]) : "r"(addr));
}
__device__ __forceinline__ void ldsm_x4_t(uint32_t* r, uint32_t addr) {
    asm volatile("ldmatrix.sync.aligned.m8n8.x4.trans.shared.b16 {%0,%1,%2,%3}, [%4];"
                 : "=r"(r[0]), "=r"(r[1]), "=r"(r[2]), "=r"(r[3]) : "r"(addr));
}
__device__ __forceinline__ void mma_f16(float* c, const uint32_t* a, const uint32_t* b) {
    asm volatile(
        "mma.sync.aligned.m16n8k16.row.col.f32.f16.f16.f32 "
        "{%0,%1,%2,%3}, {%4,%5,%6,%7}, {%8,%9}, {%0,%1,%2,%3};"
        : "+f"(c[0]), "+f"(c[1]), "+f"(c[2]), "+f"(c[3])
        : "r"(a[0]), "r"(a[1]), "r"(a[2]), "r"(a[3]), "r"(b[0]), "r"(b[1]));
}

// ---------------- merged pre-pass: fp32 -> fp16(rn), 3 segments ----------------
__global__ void to_half_all(const float4* __restrict__ x,
                            const float4* __restrict__ w1,
                            const float4* __restrict__ w2,
                            uint2* __restrict__ xh,
                            uint2* __restrict__ w1h,
                            uint2* __restrict__ w2h,
                            int nx, int nw1, int nw2)
{
    const int total = nx + nw1 + nw2;
    int i = blockIdx.x * blockDim.x + threadIdx.x;
    const int stride = gridDim.x * blockDim.x;
    for (; i < total; i += stride) {
        const float4* s; uint2* d; int j = i;
        if (j < nx)            { s = x;  d = xh; }
        else if (j < nx + nw1) { j -= nx;       s = w1; d = w1h; }
        else                   { j -= nx + nw1; s = w2; d = w2h; }
        float4 v = s[j];
        __half2 h0 = __floats2half2_rn(v.x, v.y);
        __half2 h1 = __floats2half2_rn(v.z, v.w);
        uint2 u;
        u.x = *reinterpret_cast<uint32_t*>(&h0);
        u.y = *reinterpret_cast<uint32_t*>(&h1);
        d[j] = u;
    }
}

// ----------------------------------------------------------------------------
// C 128x128 tile = A[128, K] @ W[K, NTOT slice 128]  (+bias, optional SwiGLU)
// ----------------------------------------------------------------------------
template <bool FUSE, int NTOT, typename OutT>
__global__ __launch_bounds__(256, 2)
void hmma_gemm_kernel(const __half* __restrict__ Ag,
                      const __half* __restrict__ Wg,
                      const float* __restrict__ biasg,
                      OutT* __restrict__ Cg)
{
    extern __shared__ float dsm[];
    const int tid  = threadIdx.x;
    const int wid  = tid >> 5;
    const int lane = tid & 31;
    const int e  = blockIdx.z;
    const int bm = blockIdx.y * BM;
    const int bn = blockIdx.x * BN;

    const __half* Ae = Ag + ((size_t)e * T_ + bm) * D_;
    const __half* We = Wg + (size_t)e * D_ * NTOT + bn;
    const float*  Be = biasg + (size_t)e * NTOT + bn;

    const uint32_t s0 = (smem_u32(dsm) + 127u) & ~127u;

    // --- producer state: A = 1024 chunks (4/thr), B = 1024 chunks (4/thr) ---
    const int pArow = tid >> 3, pAc = tid & 7;
    const uint32_t pAoff = swzA(pArow, pAc);
    const uint32_t pAg   = (uint32_t)pArow * D_ + pAc * 8;
    const int pBk = tid >> 4, pBc = tid & 15;
    const uint32_t pBoff = (uint32_t)pBk * BPITCH + pBc * 16;
    const uint32_t pBg   = (uint32_t)pBk * NTOT + pBc * 8;

    const __half* aSrc = Ae;
    const __half* bSrc = We;
    auto produce = [&](uint32_t base) {
        #pragma unroll
        for (int i = 0; i < 4; i++)
            cpasync16(base + pAoff + i * (32u * 128u),
                      aSrc + pAg + (size_t)(32 * i) * D_);
        const uint32_t pb = base + A_STAGE_B;
        #pragma unroll
        for (int i = 0; i < 4; i++)
            cpasync16(pb + pBoff + i * (16u * BPITCH),
                      bSrc + pBg + (size_t)(16 * i) * NTOT);
        cp_commit();
        aSrc += BK;
        bSrc += (size_t)BK * NTOT;
    };

    const int wm = (wid >> 2) * 64;
    const int wn = (wid & 3) * 32;

    float acc[4][4][4];
    #pragma unroll
    for (int mi = 0; mi < 4; mi++)
        #pragma unroll
        for (int ni = 0; ni < 4; ni++)
            #pragma unroll
            for (int v = 0; v < 4; v++) acc[mi][ni][v] = 0.0f;

    const int lrow = lane & 15;
    const int lchx = lane >> 4;
    const uint32_t rx = (uint32_t)(lrow & 7);
    uint32_t aRowOff[4];
    #pragma unroll
    for (int mi = 0; mi < 4; mi++)
        aRowOff[mi] = (uint32_t)(wm + mi * 16 + lrow) * 128u;
    const uint32_t bLaneOff = (uint32_t)(lane & 15) * BPITCH
                            + (uint32_t)((wn >> 3) + (lane >> 4)) * 16u;

    // consume one k-tile resident at stage base sA
    auto consume = [&](uint32_t sA) {
        const uint32_t sBl = sA + A_STAGE_B + bLaneOff;
        uint32_t b[2][4][2];
        {
            uint32_t r[4];
            ldsm_x4_t(r, sBl);
            b[0][0][0]=r[0]; b[0][0][1]=r[1]; b[0][1][0]=r[2]; b[0][1][1]=r[3];
            ldsm_x4_t(r, sBl + 32u);
            b[0][2][0]=r[0]; b[0][2][1]=r[1]; b[0][3][0]=r[2]; b[0][3][1]=r[3];
        }
        #pragma unroll
        for (int ks = 0; ks < 4; ks++) {
            uint32_t a[4][4];
            #pragma unroll
            for (int mi = 0; mi < 4; mi++) {
                uint32_t ch = ((uint32_t)(2 * ks + lchx) ^ rx) * 16u;
                ldsm_x4(a[mi], sA + aRowOff[mi] + ch);
            }
            if (ks < 3) {
                const uint32_t nb = sBl + (uint32_t)(ks + 1) * (16u * BPITCH);
                uint32_t r[4];
                ldsm_x4_t(r, nb);
                b[(ks+1)&1][0][0]=r[0]; b[(ks+1)&1][0][1]=r[1];
                b[(ks+1)&1][1][0]=r[2]; b[(ks+1)&1][1][1]=r[3];
                ldsm_x4_t(r, nb + 32u);
                b[(ks+1)&1][2][0]=r[0]; b[(ks+1)&1][2][1]=r[1];
                b[(ks+1)&1][3][0]=r[2]; b[(ks+1)&1][3][1]=r[3];
            }
            #pragma unroll
            for (int mi = 0; mi < 4; mi++)
                #pragma unroll
                for (int ni = 0; ni < 4; ni++)
                    mma_f16(acc[mi][ni], a[mi], b[ks & 1][ni]);
        }
    };

    const uint32_t st0 = s0, st1 = s0 + STAGE_B, st2 = s0 + 2 * STAGE_B;

    // prologue: kt=0 -> stage0, kt=1 -> stage1
    produce(st0);
    produce(st1);

    // 10 rounds x 3 k-tiles (kt = 0..29), all stage addresses compile-time
    #pragma unroll 1
    for (int r = 0; r < NT / 3; r++) {
        cp_wait<1>(); __syncthreads();
        produce(st2);                 // kt+2, stage (kt+2)%3 == 2
        consume(st0);
        cp_wait<1>(); __syncthreads();
        produce(st0);
        consume(st1);
        cp_wait<1>(); __syncthreads();
        produce(st1);
        consume(st2);
    }
    // tail: kt=30 (stage0), kt=31 (stage1); nothing left to produce
    cp_wait<1>(); __syncthreads();
    consume(st0);
    cp_wait<0>(); __syncthreads();
    consume(st1);

    // ------------------------------ epilogue (direct stores, R8-verified) ----
    #pragma unroll
    for (int ni = 0; ni < 4; ni++) {
        const int cl = wn + ni * 8 + 2 * (lane & 3);
        const float b_e = Be[cl];
        const float b_o = Be[cl + 1];
        #pragma unroll
        for (int mi = 0; mi < 4; mi++) {
            const int r0 = bm + wm + mi * 16 + (lane >> 2);
            #pragma unroll
            for (int h = 0; h < 2; h++) {
                const float v0 = acc[mi][ni][2 * h + 0] + b_e;
                const float v1 = acc[mi][ni][2 * h + 1] + b_o;
                const size_t row = (size_t)e * T_ + r0 + 8 * h;
                if (FUSE) {
                    float g = fminf(v0, LIMIT_);
                    float l = fminf(fmaxf(v1, -LIMIT_), LIMIT_);
                    float sg = 1.0f / (1.0f + __expf(-ALPHA_ * g));
                    ((__half*)Cg)[row * D_ + ((bn + cl) >> 1)] =
                        __float2half_rn(g * sg * (l + 1.0f));
                } else {
                    float2 o = make_float2(v0, v1);
                    *(float2*)((float*)Cg + row * D_ + bn + cl) = o;
                }
            }
        }
    }
}

// ----------------------------------------------------------------------------
extern "C" void kernel_launch(void* const* d_in, const int* in_sizes, int n_in,
                              void* d_out, int out_size)
{
    (void)in_sizes; (void)n_in; (void)out_size;
    const float* x  = (const float*)d_in[0];
    const float* w1 = (const float*)d_in[1];
    const float* b1 = (const float*)d_in[2];
    const float* w2 = (const float*)d_in[3];
    const float* b2 = (const float*)d_in[4];
    float* out = (float*)d_out;

    __half *acth, *xh, *w1h, *w2h;
    cudaGetSymbolAddress((void**)&acth, g_acth);
    cudaGetSymbolAddress((void**)&xh,   g_xh);
    cudaGetSymbolAddress((void**)&w1h,  g_w1h);
    cudaGetSymbolAddress((void**)&w2h,  g_w2h);

    static bool attr_done = false;
    if (!attr_done) {
        cudaFuncSetAttribute(hmma_gemm_kernel<true,  F_, __half>,
                             cudaFuncAttributeMaxDynamicSharedMemorySize, SMEM_BYTES);
        cudaFuncSetAttribute(hmma_gemm_kernel<false, D_, float>,
                             cudaFuncAttributeMaxDynamicSharedMemorySize, SMEM_BYTES);
        attr_done = true;
    }

    // merged pre-pass: fp32 -> fp16 once (x, w1, w2)
    const int nx  = E_ * T_ * D_ / 4;
    const int nw1 = E_ * D_ * F_ / 4;
    const int nw2 = E_ * D_ * D_ / 4;
    to_half_all<<<4096, 256>>>((const float4*)x, (const float4*)w1, (const float4*)w2,
                               (uint2*)xh, (uint2*)w1h, (uint2*)w2h, nx, nw1, nw2);

    // GEMM1 + bias + SwiGLU -> act (fp16)   (M=2048, N=4096, K=2048)
    dim3 g1(F_ / BN, T_ / BM, E_);
    hmma_gemm_kernel<true,  F_, __half><<<g1, 256, SMEM_BYTES>>>(xh, w1h, b1, acth);

    // GEMM2 + bias -> out (fp32)            (M=2048, N=2048, K=2048)
    dim3 g2(D_ / BN, T_ / BM, E_);
    hmma_gemm_kernel<false, D_, float><<<g2, 256, SMEM_BYTES>>>(acth, w2h, b2, out);
}

// round 12
// speedup vs baseline: 1.1043x; 1.0301x over previous
#include <cuda_runtime.h>
#include <cuda_fp16.h>
#include <cstdint>

// ============================================================================
// GroupedExperts: out = swiglu(x@W1+b1) @ W2 + b2   (E=8, T=2048, D=2048)
// R12: R11's fp16 mma.sync pipeline with per-stage mbarrier producer/consumer
// sync replacing wait_group+__syncthreads (warp decoupling across k-tiles).
// Merged fp32->fp16 prepass; direct-store epilogues (R8-verified).
// ============================================================================

namespace {
constexpr int E_ = 8;
constexpr int T_ = 2048;
constexpr int D_ = 2048;
constexpr int F_ = 4096;

constexpr int BM = 128, BN = 128, BK = 64;
constexpr int NT = D_ / BK;                   // 32 k-tiles (K=2048 both GEMMs)

constexpr int BPITCH = 272;                   // B row pitch bytes (conflict-free)
constexpr int A_STAGE_B = BM * BK * 2;        // 16384 B (128 rows x 128B)
constexpr int B_STAGE_B = BK * BPITCH;        // 17408 B
constexpr int STAGE_B   = A_STAGE_B + B_STAGE_B;    // 33792
constexpr int SMEM_BYTES = 3 * STAGE_B + 128;       // ~99.1 KB -> 2 CTAs/SM

constexpr float ALPHA_ = 1.702f;
constexpr float LIMIT_ = 7.0f;
}

// scratch (no allocations allowed): fp16 copies + fp16 activation
__device__ __half g_acth[(size_t)E_ * T_ * D_];   // 64 MiB
__device__ __half g_xh  [(size_t)E_ * T_ * D_];   // 64 MiB
__device__ __half g_w1h [(size_t)E_ * D_ * F_];   // 128 MiB
__device__ __half g_w2h [(size_t)E_ * D_ * D_];   // 64 MiB

// ---------------- PTX helpers ----------------
__device__ __forceinline__ uint32_t smem_u32(const void* p) {
    uint32_t a;
    asm("{ .reg .u64 t; cvta.to.shared.u64 t, %1; cvt.u32.u64 %0, t; }" : "=r"(a) : "l"(p));
    return a;
}
__device__ __forceinline__ uint32_t swzA(uint32_t row, uint32_t ch) {
    return row * 128u + ((ch ^ (row & 7u)) * 16u);
}
__device__ __forceinline__ void cpasync16(uint32_t dst, const void* src) {
    asm volatile("cp.async.cg.shared.global [%0], [%1], 16;" :: "r"(dst), "l"(src) : "memory");
}
__device__ __forceinline__ void cpasync_arrive(uint32_t bar) {
    asm volatile("cp.async.mbarrier.arrive.noinc.shared::cta.b64 [%0];" :: "r"(bar) : "memory");
}
__device__ __forceinline__ void mbar_init(uint32_t bar, uint32_t cnt) {
    asm volatile("mbarrier.init.shared.b64 [%0], %1;" :: "r"(bar), "r"(cnt) : "memory");
}
__device__ __forceinline__ void mbar_arrive(uint32_t bar) {
    asm volatile("mbarrier.arrive.shared.b64 _, [%0];" :: "r"(bar) : "memory");
}
__device__ __forceinline__ void mbar_wait(uint32_t bar, uint32_t parity) {
    uint32_t done;
    asm volatile(
        "{\n\t.reg .pred p;\n\t"
        "mbarrier.try_wait.parity.acquire.cta.shared::cta.b64 p, [%1], %2;\n\t"
        "selp.b32 %0, 1, 0, p;\n\t}"
        : "=r"(done) : "r"(bar), "r"(parity) : "memory");
    if (!done) {
        asm volatile(
            "{\n\t.reg .pred P1;\n\t"
            "W_%=:\n\t"
            "mbarrier.try_wait.parity.acquire.cta.shared::cta.b64 P1, [%0], %1, 0x989680;\n\t"
            "@P1 bra.uni DN_%=;\n\t"
            "bra.uni W_%=;\n\t"
            "DN_%=:\n\t}"
            :: "r"(bar), "r"(parity) : "memory");
    }
}
__device__ __forceinline__ void ldsm_x4(uint32_t* r, uint32_t addr) {
    asm volatile("ldmatrix.sync.aligned.m8n8.x4.shared.b16 {%0,%1,%2,%3}, [%4];"
                 : "=r"(r[0]), "=r"(r[1]), "=r"(r[2]), "=r"(r[3]) : "r"(addr));
}
__device__ __forceinline__ void ldsm_x4_t(uint32_t* r, uint32_t addr) {
    asm volatile("ldmatrix.sync.aligned.m8n8.x4.trans.shared.b16 {%0,%1,%2,%3}, [%4];"
                 : "=r"(r[0]), "=r"(r[1]), "=r"(r[2]), "=r"(r[3]) : "r"(addr));
}
__device__ __forceinline__ void mma_f16(float* c, const uint32_t* a, const uint32_t* b) {
    asm volatile(
        "mma.sync.aligned.m16n8k16.row.col.f32.f16.f16.f32 "
        "{%0,%1,%2,%3}, {%4,%5,%6,%7}, {%8,%9}, {%0,%1,%2,%3};"
        : "+f"(c[0]), "+f"(c[1]), "+f"(c[2]), "+f"(c[3])
        : "r"(a[0]), "r"(a[1]), "r"(a[2]), "r"(a[3]), "r"(b[0]), "r"(b[1]));
}

// ---------------- merged pre-pass: fp32 -> fp16(rn), 3 segments ----------------
__global__ void to_half_all(const float4* __restrict__ x,
                            const float4* __restrict__ w1,
                            const float4* __restrict__ w2,
                            uint2* __restrict__ xh,
                            uint2* __restrict__ w1h,
                            uint2* __restrict__ w2h,
                            int nx, int nw1, int nw2)
{
    const int total = nx + nw1 + nw2;
    int i = blockIdx.x * blockDim.x + threadIdx.x;
    const int stride = gridDim.x * blockDim.x;
    for (; i < total; i += stride) {
        const float4* s; uint2* d; int j = i;
        if (j < nx)            { s = x;  d = xh; }
        else if (j < nx + nw1) { j -= nx;       s = w1; d = w1h; }
        else                   { j -= nx + nw1; s = w2; d = w2h; }
        float4 v = s[j];
        __half2 h0 = __floats2half2_rn(v.x, v.y);
        __half2 h1 = __floats2half2_rn(v.z, v.w);
        uint2 u;
        u.x = *reinterpret_cast<uint32_t*>(&h0);
        u.y = *reinterpret_cast<uint32_t*>(&h1);
        d[j] = u;
    }
}

// ----------------------------------------------------------------------------
// C 128x128 tile = A[128, K] @ W[K, NTOT slice 128]  (+bias, optional SwiGLU)
// ----------------------------------------------------------------------------
template <bool FUSE, int NTOT, typename OutT>
__global__ __launch_bounds__(256, 2)
void hmma_gemm_kernel(const __half* __restrict__ Ag,
                      const __half* __restrict__ Wg,
                      const float* __restrict__ biasg,
                      OutT* __restrict__ Cg)
{
    extern __shared__ float dsm[];
    __shared__ __align__(8) uint64_t mbars[6];   // full0..2, empty0..2

    const int tid  = threadIdx.x;
    const int wid  = tid >> 5;
    const int lane = tid & 31;
    const int e  = blockIdx.z;
    const int bm = blockIdx.y * BM;
    const int bn = blockIdx.x * BN;

    const __half* Ae = Ag + ((size_t)e * T_ + bm) * D_;
    const __half* We = Wg + (size_t)e * D_ * NTOT + bn;
    const float*  Be = biasg + (size_t)e * NTOT + bn;

    const uint32_t s0 = (smem_u32(dsm) + 127u) & ~127u;
    const uint32_t mb = smem_u32(mbars);
    const uint32_t fb0 = mb,      fb1 = mb + 8,  fb2 = mb + 16;
    const uint32_t eb0 = mb + 24, eb1 = mb + 32, eb2 = mb + 40;

    if (tid == 0) {
        mbar_init(fb0, 256); mbar_init(fb1, 256); mbar_init(fb2, 256);
        mbar_init(eb0, 256); mbar_init(eb1, 256); mbar_init(eb2, 256);
    }
    __syncthreads();

    // --- producer state: A = 1024 chunks (4/thr), B = 1024 chunks (4/thr) ---
    const int pArow = tid >> 3, pAc = tid & 7;
    const uint32_t pAoff = swzA(pArow, pAc);
    const uint32_t pAg   = (uint32_t)pArow * D_ + pAc * 8;
    const int pBk = tid >> 4, pBc = tid & 15;
    const uint32_t pBoff = (uint32_t)pBk * BPITCH + pBc * 16;
    const uint32_t pBg   = (uint32_t)pBk * NTOT + pBc * 8;

    const __half* aSrc = Ae;
    const __half* bSrc = We;
    auto produce = [&](uint32_t base, uint32_t fbar) {
        #pragma unroll
        for (int i = 0; i < 4; i++)
            cpasync16(base + pAoff + i * (32u * 128u),
                      aSrc + pAg + (size_t)(32 * i) * D_);
        const uint32_t pb = base + A_STAGE_B;
        #pragma unroll
        for (int i = 0; i < 4; i++)
            cpasync16(pb + pBoff + i * (16u * BPITCH),
                      bSrc + pBg + (size_t)(16 * i) * NTOT);
        cpasync_arrive(fbar);
        aSrc += BK;
        bSrc += (size_t)BK * NTOT;
    };

    const int wm = (wid >> 2) * 64;
    const int wn = (wid & 3) * 32;

    float acc[4][4][4];
    #pragma unroll
    for (int mi = 0; mi < 4; mi++)
        #pragma unroll
        for (int ni = 0; ni < 4; ni++)
            #pragma unroll
            for (int v = 0; v < 4; v++) acc[mi][ni][v] = 0.0f;

    const int lrow = lane & 15;
    const int lchx = lane >> 4;
    const uint32_t rx = (uint32_t)(lrow & 7);
    uint32_t aRowOff[4];
    #pragma unroll
    for (int mi = 0; mi < 4; mi++)
        aRowOff[mi] = (uint32_t)(wm + mi * 16 + lrow) * 128u;
    const uint32_t bLaneOff = (uint32_t)(lane & 15) * BPITCH
                            + (uint32_t)((wn >> 3) + (lane >> 4)) * 16u;

    auto consume = [&](uint32_t sA) {
        const uint32_t sBl = sA + A_STAGE_B + bLaneOff;
        uint32_t b[2][4][2];
        {
            uint32_t r[4];
            ldsm_x4_t(r, sBl);
            b[0][0][0]=r[0]; b[0][0][1]=r[1]; b[0][1][0]=r[2]; b[0][1][1]=r[3];
            ldsm_x4_t(r, sBl + 32u);
            b[0][2][0]=r[0]; b[0][2][1]=r[1]; b[0][3][0]=r[2]; b[0][3][1]=r[3];
        }
        #pragma unroll
        for (int ks = 0; ks < 4; ks++) {
            uint32_t a[4][4];
            #pragma unroll
            for (int mi = 0; mi < 4; mi++) {
                uint32_t ch = ((uint32_t)(2 * ks + lchx) ^ rx) * 16u;
                ldsm_x4(a[mi], sA + aRowOff[mi] + ch);
            }
            if (ks < 3) {
                const uint32_t nb = sBl + (uint32_t)(ks + 1) * (16u * BPITCH);
                uint32_t r[4];
                ldsm_x4_t(r, nb);
                b[(ks+1)&1][0][0]=r[0]; b[(ks+1)&1][0][1]=r[1];
                b[(ks+1)&1][1][0]=r[2]; b[(ks+1)&1][1][1]=r[3];
                ldsm_x4_t(r, nb + 32u);
                b[(ks+1)&1][2][0]=r[0]; b[(ks+1)&1][2][1]=r[1];
                b[(ks+1)&1][3][0]=r[2]; b[(ks+1)&1][3][1]=r[3];
            }
            #pragma unroll
            for (int mi = 0; mi < 4; mi++)
                #pragma unroll
                for (int ni = 0; ni < 4; ni++)
                    mma_f16(acc[mi][ni], a[mi], b[ks & 1][ni]);
        }
    };

    const uint32_t st0 = s0, st1 = s0 + STAGE_B, st2 = s0 + 2 * STAGE_B;

    // per-stage parities: producer (empty) start at 1, consumer (full) at 0
    uint32_t ep0 = 1, ep1 = 1, ep2 = 1;
    uint32_t fp0 = 0, fp1 = 0, fp2 = 0;

    // prologue: kt=0 -> stage0, kt=1 -> stage1
    mbar_wait(eb0, ep0); ep0 ^= 1; produce(st0, fb0);
    mbar_wait(eb1, ep1); ep1 ^= 1; produce(st1, fb1);

    // 10 rounds x 3 k-tiles (kt = 0..29); produces serve kt 2..31
    #pragma unroll 1
    for (int r = 0; r < NT / 3; r++) {
        mbar_wait(eb2, ep2); ep2 ^= 1; produce(st2, fb2);
        mbar_wait(fb0, fp0); fp0 ^= 1; consume(st0); mbar_arrive(eb0);
        mbar_wait(eb0, ep0); ep0 ^= 1; produce(st0, fb0);
        mbar_wait(fb1, fp1); fp1 ^= 1; consume(st1); mbar_arrive(eb1);
        mbar_wait(eb1, ep1); ep1 ^= 1; produce(st1, fb1);
        mbar_wait(fb2, fp2); fp2 ^= 1; consume(st2); mbar_arrive(eb2);
    }
    // tail: kt=30 (stage0), kt=31 (stage1)
    mbar_wait(fb0, fp0); consume(st0);
    mbar_wait(fb1, fp1); consume(st1);

    // ------------------------------ epilogue (direct stores) ------------------
    #pragma unroll
    for (int ni = 0; ni < 4; ni++) {
        const int cl = wn + ni * 8 + 2 * (lane & 3);
        const float b_e = Be[cl];
        const float b_o = Be[cl + 1];
        #pragma unroll
        for (int mi = 0; mi < 4; mi++) {
            const int r0 = bm + wm + mi * 16 + (lane >> 2);
            #pragma unroll
            for (int h = 0; h < 2; h++) {
                const float v0 = acc[mi][ni][2 * h + 0] + b_e;
                const float v1 = acc[mi][ni][2 * h + 1] + b_o;
                const size_t row = (size_t)e * T_ + r0 + 8 * h;
                if (FUSE) {
                    float g = fminf(v0, LIMIT_);
                    float l = fminf(fmaxf(v1, -LIMIT_), LIMIT_);
                    float sg = 1.0f / (1.0f + __expf(-ALPHA_ * g));
                    ((__half*)Cg)[row * D_ + ((bn + cl) >> 1)] =
                        __float2half_rn(g * sg * (l + 1.0f));
                } else {
                    float2 o = make_float2(v0, v1);
                    *(float2*)((float*)Cg + row * D_ + bn + cl) = o;
                }
            }
        }
    }
}

// ----------------------------------------------------------------------------
extern "C" void kernel_launch(void* const* d_in, const int* in_sizes, int n_in,
                              void* d_out, int out_size)
{
    (void)in_sizes; (void)n_in; (void)out_size;
    const float* x  = (const float*)d_in[0];
    const float* w1 = (const float*)d_in[1];
    const float* b1 = (const float*)d_in[2];
    const float* w2 = (const float*)d_in[3];
    const float* b2 = (const float*)d_in[4];
    float* out = (float*)d_out;

    __half *acth, *xh, *w1h, *w2h;
    cudaGetSymbolAddress((void**)&acth, g_acth);
    cudaGetSymbolAddress((void**)&xh,   g_xh);
    cudaGetSymbolAddress((void**)&w1h,  g_w1h);
    cudaGetSymbolAddress((void**)&w2h,  g_w2h);

    static bool attr_done = false;
    if (!attr_done) {
        cudaFuncSetAttribute(hmma_gemm_kernel<true,  F_, __half>,
                             cudaFuncAttributeMaxDynamicSharedMemorySize, SMEM_BYTES);
        cudaFuncSetAttribute(hmma_gemm_kernel<false, D_, float>,
                             cudaFuncAttributeMaxDynamicSharedMemorySize, SMEM_BYTES);
        attr_done = true;
    }

    // merged pre-pass: fp32 -> fp16 once (x, w1, w2)
    const int nx  = E_ * T_ * D_ / 4;
    const int nw1 = E_ * D_ * F_ / 4;
    const int nw2 = E_ * D_ * D_ / 4;
    to_half_all<<<4096, 256>>>((const float4*)x, (const float4*)w1, (const float4*)w2,
                               (uint2*)xh, (uint2*)w1h, (uint2*)w2h, nx, nw1, nw2);

    // GEMM1 + bias + SwiGLU -> act (fp16)   (M=2048, N=4096, K=2048)
    dim3 g1(F_ / BN, T_ / BM, E_);
    hmma_gemm_kernel<true,  F_, __half><<<g1, 256, SMEM_BYTES>>>(xh, w1h, b1, acth);

    // GEMM2 + bias -> out (fp32)            (M=2048, N=2048, K=2048)
    dim3 g2(D_ / BN, T_ / BM, E_);
    hmma_gemm_kernel<false, D_, float><<<g2, 256, SMEM_BYTES>>>(acth, w2h, b2, out);
}

// round 13
// speedup vs baseline: 1.1393x; 1.0317x over previous
#include <cuda_runtime.h>
#include <cuda_fp16.h>
#include <cstdint>

// ============================================================================
// GroupedExperts: out = swiglu(x@W1+b1) @ W2 + b2   (E=8, T=2048, D=2048)
// R13: R12's fp16 mma.sync + mbarrier pipeline (verified), with the w2
// fp32->fp16 conversion moved OFF the critical path: prepass converts only
// x+w1; 512 converter CTAs interleaved into the GEMM1 launch convert w2
// concurrently (GEMM1 runs at 5% DRAM - free bandwidth).
// ============================================================================

namespace {
constexpr int E_ = 8;
constexpr int T_ = 2048;
constexpr int D_ = 2048;
constexpr int F_ = 4096;

constexpr int BM = 128, BN = 128, BK = 64;
constexpr int NT = D_ / BK;                   // 32 k-tiles (K=2048 both GEMMs)

constexpr int BPITCH = 272;                   // B row pitch bytes (conflict-free)
constexpr int A_STAGE_B = BM * BK * 2;        // 16384 B
constexpr int B_STAGE_B = BK * BPITCH;        // 17408 B
constexpr int STAGE_B   = A_STAGE_B + B_STAGE_B;    // 33792
constexpr int SMEM_BYTES = 3 * STAGE_B + 128;       // ~99.1 KB -> 2 CTAs/SM

constexpr int CVT_THREADS = 512 * 256;        // embedded converter thread count

constexpr float ALPHA_ = 1.702f;
constexpr float LIMIT_ = 7.0f;
}

// scratch (no allocations allowed): fp16 copies + fp16 activation
__device__ __half g_acth[(size_t)E_ * T_ * D_];   // 64 MiB
__device__ __half g_xh  [(size_t)E_ * T_ * D_];   // 64 MiB
__device__ __half g_w1h [(size_t)E_ * D_ * F_];   // 128 MiB
__device__ __half g_w2h [(size_t)E_ * D_ * D_];   // 64 MiB

// ---------------- PTX helpers ----------------
__device__ __forceinline__ uint32_t smem_u32(const void* p) {
    uint32_t a;
    asm("{ .reg .u64 t; cvta.to.shared.u64 t, %1; cvt.u32.u64 %0, t; }" : "=r"(a) : "l"(p));
    return a;
}
__device__ __forceinline__ uint32_t swzA(uint32_t row, uint32_t ch) {
    return row * 128u + ((ch ^ (row & 7u)) * 16u);
}
__device__ __forceinline__ void cpasync16(uint32_t dst, const void* src) {
    asm volatile("cp.async.cg.shared.global [%0], [%1], 16;" :: "r"(dst), "l"(src) : "memory");
}
__device__ __forceinline__ void cpasync_arrive(uint32_t bar) {
    asm volatile("cp.async.mbarrier.arrive.noinc.shared::cta.b64 [%0];" :: "r"(bar) : "memory");
}
__device__ __forceinline__ void mbar_init(uint32_t bar, uint32_t cnt) {
    asm volatile("mbarrier.init.shared.b64 [%0], %1;" :: "r"(bar), "r"(cnt) : "memory");
}
__device__ __forceinline__ void mbar_arrive(uint32_t bar) {
    asm volatile("mbarrier.arrive.shared.b64 _, [%0];" :: "r"(bar) : "memory");
}
__device__ __forceinline__ void mbar_wait(uint32_t bar, uint32_t parity) {
    uint32_t done;
    asm volatile(
        "{\n\t.reg .pred p;\n\t"
        "mbarrier.try_wait.parity.acquire.cta.shared::cta.b64 p, [%1], %2;\n\t"
        "selp.b32 %0, 1, 0, p;\n\t}"
        : "=r"(done) : "r"(bar), "r"(parity) : "memory");
    if (!done) {
        asm volatile(
            "{\n\t.reg .pred P1;\n\t"
            "W_%=:\n\t"
            "mbarrier.try_wait.parity.acquire.cta.shared::cta.b64 P1, [%0], %1, 0x989680;\n\t"
            "@P1 bra.uni DN_%=;\n\t"
            "bra.uni W_%=;\n\t"
            "DN_%=:\n\t}"
            :: "r"(bar), "r"(parity) : "memory");
    }
}
__device__ __forceinline__ void ldsm_x4(uint32_t* r, uint32_t addr) {
    asm volatile("ldmatrix.sync.aligned.m8n8.x4.shared.b16 {%0,%1,%2,%3}, [%4];"
                 : "=r"(r[0]), "=r"(r[1]), "=r"(r[2]), "=r"(r[3]) : "r"(addr));
}
__device__ __forceinline__ void ldsm_x4_t(uint32_t* r, uint32_t addr) {
    asm volatile("ldmatrix.sync.aligned.m8n8.x4.trans.shared.b16 {%0,%1,%2,%3}, [%4];"
                 : "=r"(r[0]), "=r"(r[1]), "=r"(r[2]), "=r"(r[3]) : "r"(addr));
}
__device__ __forceinline__ void mma_f16(float* c, const uint32_t* a, const uint32_t* b) {
    asm volatile(
        "mma.sync.aligned.m16n8k16.row.col.f32.f16.f16.f32 "
        "{%0,%1,%2,%3}, {%4,%5,%6,%7}, {%8,%9}, {%0,%1,%2,%3};"
        : "+f"(c[0]), "+f"(c[1]), "+f"(c[2]), "+f"(c[3])
        : "r"(a[0]), "r"(a[1]), "r"(a[2]), "r"(a[3]), "r"(b[0]), "r"(b[1]));
}
__device__ __forceinline__ uint2 f4_to_h4(float4 v) {
    __half2 h0 = __floats2half2_rn(v.x, v.y);
    __half2 h1 = __floats2half2_rn(v.z, v.w);
    uint2 u;
    u.x = *reinterpret_cast<uint32_t*>(&h0);
    u.y = *reinterpret_cast<uint32_t*>(&h1);
    return u;
}

// ---------------- pre-pass: fp32 -> fp16(rn) for x + w1 only ----------------
__global__ void to_half_xw1(const float4* __restrict__ x,
                            const float4* __restrict__ w1,
                            uint2* __restrict__ xh,
                            uint2* __restrict__ w1h,
                            int nx, int nw1)
{
    const int total = nx + nw1;
    const int stride = gridDim.x * blockDim.x;
    int i = blockIdx.x * blockDim.x + threadIdx.x;
    auto one = [&](int j) {
        float4 v; uint2* d;
        if (j < nx) { v = x[j]; d = xh + j; }
        else        { v = w1[j - nx]; d = w1h + (j - nx); }
        *d = f4_to_h4(v);
    };
    #pragma unroll 1
    for (; i + 3 * stride < total; i += 4 * stride) {
        one(i); one(i + stride); one(i + 2 * stride); one(i + 3 * stride);
    }
    for (; i < total; i += stride) one(i);
}

// ----------------------------------------------------------------------------
// C 128x128 tile = A[128, K] @ W[K, NTOT slice 128]  (+bias, optional SwiGLU)
// CONVERT=true: 1D grid, 1-in-9 blocks convert cvt_src->cvt_dst instead.
// ----------------------------------------------------------------------------
template <bool FUSE, int NTOT, typename OutT, bool CONVERT>
__global__ __launch_bounds__(256, 2)
void hmma_gemm_kernel(const __half* __restrict__ Ag,
                      const __half* __restrict__ Wg,
                      const float* __restrict__ biasg,
                      OutT* __restrict__ Cg,
                      const float4* __restrict__ cvt_src,
                      uint2* __restrict__ cvt_dst,
                      int cvt_n4)
{
    extern __shared__ float dsm[];
    __shared__ __align__(8) uint64_t mbars[6];   // full0..2, empty0..2

    const int tid  = threadIdx.x;

    int bxi, byi, e;
    if (CONVERT) {
        const uint32_t cid = blockIdx.x;
        const uint32_t q = cid / 9u, r = cid - q * 9u;
        if (r == 8u) {
            // converter CTA: grid-stride fp32->fp16 over cvt (w2)
            int i = (int)(q * 256u) + tid;
            #pragma unroll 1
            for (; i + 3 * CVT_THREADS < cvt_n4; i += 4 * CVT_THREADS) {
                float4 v0 = cvt_src[i];
                float4 v1 = cvt_src[i + CVT_THREADS];
                float4 v2 = cvt_src[i + 2 * CVT_THREADS];
                float4 v3 = cvt_src[i + 3 * CVT_THREADS];
                cvt_dst[i]                   = f4_to_h4(v0);
                cvt_dst[i + CVT_THREADS]     = f4_to_h4(v1);
                cvt_dst[i + 2 * CVT_THREADS] = f4_to_h4(v2);
                cvt_dst[i + 3 * CVT_THREADS] = f4_to_h4(v3);
            }
            for (; i < cvt_n4; i += CVT_THREADS) cvt_dst[i] = f4_to_h4(cvt_src[i]);
            return;
        }
        const uint32_t id = q * 8u + r;          // 0..4095
        e   = (int)(id >> 9);
        byi = (int)((id >> 5) & 15u);
        bxi = (int)(id & 31u);
    } else {
        bxi = blockIdx.x; byi = blockIdx.y; e = blockIdx.z;
    }

    const int wid  = tid >> 5;
    const int lane = tid & 31;
    const int bm = byi * BM;
    const int bn = bxi * BN;

    const __half* Ae = Ag + ((size_t)e * T_ + bm) * D_;
    const __half* We = Wg + (size_t)e * D_ * NTOT + bn;
    const float*  Be = biasg + (size_t)e * NTOT + bn;

    const uint32_t s0 = (smem_u32(dsm) + 127u) & ~127u;
    const uint32_t mb = smem_u32(mbars);
    const uint32_t fb0 = mb,      fb1 = mb + 8,  fb2 = mb + 16;
    const uint32_t eb0 = mb + 24, eb1 = mb + 32, eb2 = mb + 40;

    if (tid == 0) {
        mbar_init(fb0, 256); mbar_init(fb1, 256); mbar_init(fb2, 256);
        mbar_init(eb0, 256); mbar_init(eb1, 256); mbar_init(eb2, 256);
    }
    __syncthreads();

    // --- producer state ---
    const int pArow = tid >> 3, pAc = tid & 7;
    const uint32_t pAoff = swzA(pArow, pAc);
    const uint32_t pAg   = (uint32_t)pArow * D_ + pAc * 8;
    const int pBk = tid >> 4, pBc = tid & 15;
    const uint32_t pBoff = (uint32_t)pBk * BPITCH + pBc * 16;
    const uint32_t pBg   = (uint32_t)pBk * NTOT + pBc * 8;

    const __half* aSrc = Ae;
    const __half* bSrc = We;
    auto produce = [&](uint32_t base, uint32_t fbar) {
        #pragma unroll
        for (int i = 0; i < 4; i++)
            cpasync16(base + pAoff + i * (32u * 128u),
                      aSrc + pAg + (size_t)(32 * i) * D_);
        const uint32_t pb = base + A_STAGE_B;
        #pragma unroll
        for (int i = 0; i < 4; i++)
            cpasync16(pb + pBoff + i * (16u * BPITCH),
                      bSrc + pBg + (size_t)(16 * i) * NTOT);
        cpasync_arrive(fbar);
        aSrc += BK;
        bSrc += (size_t)BK * NTOT;
    };

    const int wm = (wid >> 2) * 64;
    const int wn = (wid & 3) * 32;

    float acc[4][4][4];
    #pragma unroll
    for (int mi = 0; mi < 4; mi++)
        #pragma unroll
        for (int ni = 0; ni < 4; ni++)
            #pragma unroll
            for (int v = 0; v < 4; v++) acc[mi][ni][v] = 0.0f;

    const int lrow = lane & 15;
    const int lchx = lane >> 4;
    const uint32_t rx = (uint32_t)(lrow & 7);
    uint32_t aRowOff[4];
    #pragma unroll
    for (int mi = 0; mi < 4; mi++)
        aRowOff[mi] = (uint32_t)(wm + mi * 16 + lrow) * 128u;
    const uint32_t bLaneOff = (uint32_t)(lane & 15) * BPITCH
                            + (uint32_t)((wn >> 3) + (lane >> 4)) * 16u;

    auto consume = [&](uint32_t sA) {
        const uint32_t sBl = sA + A_STAGE_B + bLaneOff;
        uint32_t b[2][4][2];
        {
            uint32_t r[4];
            ldsm_x4_t(r, sBl);
            b[0][0][0]=r[0]; b[0][0][1]=r[1]; b[0][1][0]=r[2]; b[0][1][1]=r[3];
            ldsm_x4_t(r, sBl + 32u);
            b[0][2][0]=r[0]; b[0][2][1]=r[1]; b[0][3][0]=r[2]; b[0][3][1]=r[3];
        }
        #pragma unroll
        for (int ks = 0; ks < 4; ks++) {
            uint32_t a[4][4];
            #pragma unroll
            for (int mi = 0; mi < 4; mi++) {
                uint32_t ch = ((uint32_t)(2 * ks + lchx) ^ rx) * 16u;
                ldsm_x4(a[mi], sA + aRowOff[mi] + ch);
            }
            if (ks < 3) {
                const uint32_t nb = sBl + (uint32_t)(ks + 1) * (16u * BPITCH);
                uint32_t r[4];
                ldsm_x4_t(r, nb);
                b[(ks+1)&1][0][0]=r[0]; b[(ks+1)&1][0][1]=r[1];
                b[(ks+1)&1][1][0]=r[2]; b[(ks+1)&1][1][1]=r[3];
                ldsm_x4_t(r, nb + 32u);
                b[(ks+1)&1][2][0]=r[0]; b[(ks+1)&1][2][1]=r[1];
                b[(ks+1)&1][3][0]=r[2]; b[(ks+1)&1][3][1]=r[3];
            }
            #pragma unroll
            for (int mi = 0; mi < 4; mi++)
                #pragma unroll
                for (int ni = 0; ni < 4; ni++)
                    mma_f16(acc[mi][ni], a[mi], b[ks & 1][ni]);
        }
    };

    const uint32_t st0 = s0, st1 = s0 + STAGE_B, st2 = s0 + 2 * STAGE_B;

    uint32_t ep0 = 1, ep1 = 1, ep2 = 1;
    uint32_t fp0 = 0, fp1 = 0, fp2 = 0;

    mbar_wait(eb0, ep0); ep0 ^= 1; produce(st0, fb0);
    mbar_wait(eb1, ep1); ep1 ^= 1; produce(st1, fb1);

    #pragma unroll 1
    for (int r = 0; r < NT / 3; r++) {
        mbar_wait(eb2, ep2); ep2 ^= 1; produce(st2, fb2);
        mbar_wait(fb0, fp0); fp0 ^= 1; consume(st0); mbar_arrive(eb0);
        mbar_wait(eb0, ep0); ep0 ^= 1; produce(st0, fb0);
        mbar_wait(fb1, fp1); fp1 ^= 1; consume(st1); mbar_arrive(eb1);
        mbar_wait(eb1, ep1); ep1 ^= 1; produce(st1, fb1);
        mbar_wait(fb2, fp2); fp2 ^= 1; consume(st2); mbar_arrive(eb2);
    }
    mbar_wait(fb0, fp0); consume(st0);
    mbar_wait(fb1, fp1); consume(st1);

    // ------------------------------ epilogue ------------------------------
    #pragma unroll
    for (int ni = 0; ni < 4; ni++) {
        const int cl = wn + ni * 8 + 2 * (lane & 3);
        const float b_e = Be[cl];
        const float b_o = Be[cl + 1];
        #pragma unroll
        for (int mi = 0; mi < 4; mi++) {
            const int r0 = bm + wm + mi * 16 + (lane >> 2);
            #pragma unroll
            for (int h = 0; h < 2; h++) {
                const float v0 = acc[mi][ni][2 * h + 0] + b_e;
                const float v1 = acc[mi][ni][2 * h + 1] + b_o;
                const size_t row = (size_t)e * T_ + r0 + 8 * h;
                if (FUSE) {
                    float g = fminf(v0, LIMIT_);
                    float l = fminf(fmaxf(v1, -LIMIT_), LIMIT_);
                    float sg = 1.0f / (1.0f + __expf(-ALPHA_ * g));
                    ((__half*)Cg)[row * D_ + ((bn + cl) >> 1)] =
                        __float2half_rn(g * sg * (l + 1.0f));
                } else {
                    float2 o = make_float2(v0, v1);
                    *(float2*)((float*)Cg + row * D_ + bn + cl) = o;
                }
            }
        }
    }
}

// ----------------------------------------------------------------------------
extern "C" void kernel_launch(void* const* d_in, const int* in_sizes, int n_in,
                              void* d_out, int out_size)
{
    (void)in_sizes; (void)n_in; (void)out_size;
    const float* x  = (const float*)d_in[0];
    const float* w1 = (const float*)d_in[1];
    const float* b1 = (const float*)d_in[2];
    const float* w2 = (const float*)d_in[3];
    const float* b2 = (const float*)d_in[4];
    float* out = (float*)d_out;

    __half *acth, *xh, *w1h, *w2h;
    cudaGetSymbolAddress((void**)&acth, g_acth);
    cudaGetSymbolAddress((void**)&xh,   g_xh);
    cudaGetSymbolAddress((void**)&w1h,  g_w1h);
    cudaGetSymbolAddress((void**)&w2h,  g_w2h);

    static bool attr_done = false;
    if (!attr_done) {
        cudaFuncSetAttribute(hmma_gemm_kernel<true,  F_, __half, true>,
                             cudaFuncAttributeMaxDynamicSharedMemorySize, SMEM_BYTES);
        cudaFuncSetAttribute(hmma_gemm_kernel<false, D_, float, false>,
                             cudaFuncAttributeMaxDynamicSharedMemorySize, SMEM_BYTES);
        attr_done = true;
    }

    const int nx  = E_ * T_ * D_ / 4;
    const int nw1 = E_ * D_ * F_ / 4;
    const int nw2 = E_ * D_ * D_ / 4;

    // pre-pass (critical path): x + w1 only
    to_half_xw1<<<4096, 256>>>((const float4*)x, (const float4*)w1,
                               (uint2*)xh, (uint2*)w1h, nx, nw1);

    // GEMM1 (+ embedded w2 conversion in 1-of-9 CTAs)
    // 4608 blocks = 4096 compute (32x16x8) + 512 converters
    hmma_gemm_kernel<true, F_, __half, true><<<4608, 256, SMEM_BYTES>>>(
        xh, w1h, b1, acth, (const float4*)w2, (uint2*)w2h, nw2);

    // GEMM2 + bias -> out (fp32)
    dim3 g2(D_ / BN, T_ / BM, E_);
    hmma_gemm_kernel<false, D_, float, false><<<g2, 256, SMEM_BYTES>>>(
        acth, w2h, b2, out, nullptr, nullptr, 0);
}